// round 15
// baseline (speedup 1.0000x reference)
#include <cuda_runtime.h>

// TorchGrouper — round 15: clean double-buffered cp.async pipeline.
// iter g: (A) issue cp.async group gn -> tile[1-p] (reads s_idx[pi])
//         (B) voxel-prefetch gnn -> regs; ballots -> s_ball[1-pi]
//         (C) wait_group 1 (tile[p] landed last iter); __syncthreads
//         (D) drain tile[p] -> out[g]; gpf[g]; mask(gn) from s_ball[pi]
//         (E) publish idx(gnn) -> s_idx[1-pi]; __syncthreads
// Output: [C,G,K] features, [4,G,K] gpf, [G] mask (float 1/0).

#define ZDIM 40
#define YDIM 400
#define XDIM 400
#define KK 64
#define CC 64
#define TPB 256
#define NBLK 1184

__global__ __launch_bounds__(TPB, 6) void grouper_kernel(
    const int* __restrict__ vox,     // [N,Z,Y,X]
    const int* __restrict__ gpos,    // [G,4]
    const float* __restrict__ feat,  // [M,C]
    const int* __restrict__ off,     // [K,4]
    float* __restrict__ out,
    int G)
{
    __shared__ int      s_idx[2][KK];
    __shared__ unsigned s_ball[2][2];
    __shared__ float4   s_tile[2][KK * 16];   // XOR-swizzled [k][cq'], 2x16KB

    const int t    = threadIdx.x;
    const int w    = t >> 5;
    const int lane = t & 31;
    const size_t GK = (size_t)G * KK;
    float* out_gpf  = out + (size_t)CC * GK;
    float* out_mask = out + (size_t)(CC + 4) * GK;

    // loop-invariant constants
    const int gpf_ch = t >> 6;
    const int gpf_k  = t & 63;
    const float gpf_val = (float)off[gpf_k * 4 + gpf_ch];
    int4 of = make_int4(0, 0, 0, 0);
    if (t < KK) of = reinterpret_cast<const int4*>(off)[t];

    // drain mapping (conflict-free): lane -> (ql, dc)
    const int ql = lane & 7;
    const int dc = lane >> 3;

    const int g0 = blockIdx.x;

    // ---- prologue: lookups g0 -> buf0, g0+NBLK -> buf1 ----
    if (t < KK) {
        {
            const int4 gp = reinterpret_cast<const int4*>(gpos)[g0];
            int z = min(max(gp.y + of.y, 0), ZDIM - 1);
            int y = min(max(gp.z + of.z, 0), YDIM - 1);
            int x = min(max(gp.w + of.w, 0), XDIM - 1);
            int idx = vox[((gp.x * ZDIM + z) * YDIM + y) * XDIM + x];
            s_idx[0][t] = idx;
            unsigned m = __ballot_sync(0xffffffffu, idx >= 0);
            if (lane == 0) s_ball[0][w] = m;
        }
        if (g0 + NBLK < G) {
            const int4 gp = reinterpret_cast<const int4*>(gpos)[g0 + NBLK];
            int z = min(max(gp.y + of.y, 0), ZDIM - 1);
            int y = min(max(gp.z + of.z, 0), YDIM - 1);
            int x = min(max(gp.w + of.w, 0), XDIM - 1);
            int idx = vox[((gp.x * ZDIM + z) * YDIM + y) * XDIM + x];
            s_idx[1][t] = idx;
            unsigned m = __ballot_sync(0xffffffffu, idx >= 0);
            if (lane == 0) s_ball[1][w] = m;
        }
    }
    __syncthreads();

    if (t == 0)
        out_mask[g0] = ((s_ball[0][0] | s_ball[0][1]) == 0u) ? 1.0f : 0.0f;

    // ---- issue first gather: g0 -> tile[0] ----
    {
        const unsigned tb = (unsigned)__cvta_generic_to_shared(s_tile[0]);
#pragma unroll
        for (int j = 0; j < 4; j++) {
            const int job = t + TPB * j;
            const int k   = job >> 4;
            const int cq  = job & 15;
            const int idx = s_idx[0][k];
            const unsigned dst = tb + (k * 16 + (cq ^ ((k >> 2) & 15))) * 16;
            const float* src = feat + (size_t)max(idx, 0) * CC + cq * 4;
            const int srcsz = (idx >= 0) ? 16 : 0;
            asm volatile("cp.async.cg.shared.global [%0], [%1], 16, %2;"
                         :: "r"(dst), "l"(src), "r"(srcsz));
        }
        asm volatile("cp.async.commit_group;");
    }

    // ---- main loop ----
    int p = 0, pi = 1;
    for (int g = g0; g < G; g += NBLK) {
        const int gn  = g + NBLK;
        const int gnn = g + 2 * NBLK;
        const bool hn = (gn < G);

        // (A) issue gather for gn -> tile[1-p]  (reads s_idx[pi])
        if (hn) {
            const unsigned tb = (unsigned)__cvta_generic_to_shared(s_tile[1 - p]);
#pragma unroll
            for (int j = 0; j < 4; j++) {
                const int job = t + TPB * j;
                const int k   = job >> 4;
                const int cq  = job & 15;
                const int idx = s_idx[pi][k];
                const unsigned dst = tb + (k * 16 + (cq ^ ((k >> 2) & 15))) * 16;
                const float* src = feat + (size_t)max(idx, 0) * CC + cq * 4;
                const int srcsz = (idx >= 0) ? 16 : 0;
                asm volatile("cp.async.cg.shared.global [%0], [%1], 16, %2;"
                             :: "r"(dst), "l"(src), "r"(srcsz));
            }
            asm volatile("cp.async.commit_group;");
        }

        // (B) voxel prefetch gnn -> regs; ballots -> s_ball[1-pi]
        int idxnext = -1;
        if (t < KK && gnn < G) {
            const int4 gp = reinterpret_cast<const int4*>(gpos)[gnn];
            int z = min(max(gp.y + of.y, 0), ZDIM - 1);
            int y = min(max(gp.z + of.z, 0), YDIM - 1);
            int x = min(max(gp.w + of.w, 0), XDIM - 1);
            idxnext = vox[((gp.x * ZDIM + z) * YDIM + y) * XDIM + x];
            unsigned m = __ballot_sync(0xffffffffu, idxnext >= 0);
            if (lane == 0) s_ball[1 - pi][w] = m;
        }

        // (C) wait for tile[p]'s group; deep wait only at tail
        if (hn) { asm volatile("cp.async.wait_group 1;"); }
        else    { asm volatile("cp.async.wait_group 0;"); }
        __syncthreads();

        // (D) drain tile[p] -> out[g]; gpf; mask(gn) from s_ball[pi]
        const float* tf = reinterpret_cast<const float*>(s_tile[p]);
#pragma unroll
        for (int j = 0; j < 4; j++) {
            const int task = w * 4 + j;
            const int c0   = (task & 15) * 4;
            const int qh   = task >> 4;
            const int q    = qh * 8 + ql;
            const int c    = c0 + dc;
            const int cq0  = c0 >> 2;
            float4 v;
            v.x = tf[((q * 4 + 0) * 16 + (cq0 ^ (q & 15))) * 4 + dc];
            v.y = tf[((q * 4 + 1) * 16 + (cq0 ^ (q & 15))) * 4 + dc];
            v.z = tf[((q * 4 + 2) * 16 + (cq0 ^ (q & 15))) * 4 + dc];
            v.w = tf[((q * 4 + 3) * 16 + (cq0 ^ (q & 15))) * 4 + dc];
            __stcs(reinterpret_cast<float4*>(
                       out + (size_t)c * GK + (size_t)g * KK + q * 4), v);
        }
        __stcs(out_gpf + (size_t)gpf_ch * GK + (size_t)g * KK + gpf_k, gpf_val);
        if (t == 0 && hn)
            out_mask[gn] = ((s_ball[pi][0] | s_ball[pi][1]) == 0u) ? 1.0f : 0.0f;

        // (E) publish idx(gnn) -> s_idx[1-pi]
        if (t < KK && gnn < G)
            s_idx[1 - pi][t] = idxnext;

        __syncthreads();
        p ^= 1; pi ^= 1;
    }
}

extern "C" void kernel_launch(void* const* d_in, const int* in_sizes, int n_in,
                              void* d_out, int out_size) {
    const int*   vox  = (const int*)d_in[0];
    const int*   gpos = (const int*)d_in[1];
    const float* feat = (const float*)d_in[2];
    const int*   off  = (const int*)d_in[3];
    float* out = (float*)d_out;

    const int G = in_sizes[1] / 4;   // 30000
    grouper_kernel<<<NBLK, TPB>>>(vox, gpos, feat, off, out, G);
}

// round 16
// speedup vs baseline: 1.0872x; 1.0872x over previous
#include <cuda_runtime.h>

// TorchGrouper — round 16: single 16KB tile, HALF-TILE ping-pong cp.async
// pipeline (zero extra smem -> keeps 8 blocks/SM).
// Halves: A = k 0..31 (gather jobs j=0,1; drain j=0,1), B = k 32..63.
// iter g (pending A(g),B(g)):
//   prefetch idx(g+2) | wait 1; sync | drain A | sync | issue A(g+1)
//   | wait 1; sync | drain B + gpf + mask(g+1) | publish idx | sync
//   | issue B(g+1)
// Output: [C,G,K] features, [4,G,K] gpf, [G] mask (float 1/0).

#define ZDIM 40
#define YDIM 400
#define XDIM 400
#define KK 64
#define CC 64
#define TPB 256
#define NBLK 1184

__global__ __launch_bounds__(TPB, 8) void grouper_kernel(
    const int* __restrict__ vox,     // [N,Z,Y,X]
    const int* __restrict__ gpos,    // [G,4]
    const float* __restrict__ feat,  // [M,C]
    const int* __restrict__ off,     // [K,4]
    float* __restrict__ out,
    int G)
{
    __shared__ int      s_idx[2][KK];
    __shared__ unsigned s_ball[2][2];
    __shared__ float4   s_tile[KK * 16];   // XOR-swizzled [k][cq'], 16 KB

    const int t    = threadIdx.x;
    const int w    = t >> 5;
    const int lane = t & 31;
    const size_t GK = (size_t)G * KK;
    float* out_gpf  = out + (size_t)CC * GK;
    float* out_mask = out + (size_t)(CC + 4) * GK;
    const unsigned tb = (unsigned)__cvta_generic_to_shared(s_tile);
    const float* tf = reinterpret_cast<const float*>(s_tile);

    // loop-invariant constants
    const int gpf_ch = t >> 6;
    const int gpf_k  = t & 63;
    const float gpf_val = (float)off[gpf_k * 4 + gpf_ch];
    int4 of = make_int4(0, 0, 0, 0);
    if (t < KK) of = reinterpret_cast<const int4*>(off)[t];

    // drain mapping (conflict-free): lane -> (ql, dc)
    const int ql = lane & 7;
    const int dc = lane >> 3;

    const int g0 = blockIdx.x;

    // ---- helpers as macros to keep code identical per half ----
#define ISSUE_HALF(BUF, JA, JB)                                              \
    do {                                                                     \
        _Pragma("unroll")                                                    \
        for (int j = (JA); j <= (JB); j++) {                                 \
            const int job = t + TPB * j;                                     \
            const int k   = job >> 4;                                        \
            const int cq  = job & 15;                                        \
            const int idx = s_idx[BUF][k];                                   \
            const unsigned dst = tb + (k * 16 + (cq ^ ((k >> 2) & 15))) * 16;\
            const float* src = feat + (size_t)max(idx, 0) * CC + cq * 4;     \
            const int srcsz = (idx >= 0) ? 16 : 0;                           \
            asm volatile("cp.async.cg.shared.global [%0], [%1], 16, %2;"     \
                         :: "r"(dst), "l"(src), "r"(srcsz));                 \
        }                                                                    \
        asm volatile("cp.async.commit_group;");                              \
    } while (0)

#define DRAIN_HALF(GOUT, JA, JB)                                             \
    do {                                                                     \
        _Pragma("unroll")                                                    \
        for (int j = (JA); j <= (JB); j++) {                                 \
            const int qh  = j >> 1;                                          \
            const int c0  = ((j & 1) * 8 + w) * 4;                           \
            const int q   = qh * 8 + ql;                                     \
            const int c   = c0 + dc;                                         \
            const int cq0 = c0 >> 2;                                         \
            float4 v;                                                        \
            v.x = tf[((q * 4 + 0) * 16 + (cq0 ^ q)) * 4 + dc];               \
            v.y = tf[((q * 4 + 1) * 16 + (cq0 ^ q)) * 4 + dc];               \
            v.z = tf[((q * 4 + 2) * 16 + (cq0 ^ q)) * 4 + dc];               \
            v.w = tf[((q * 4 + 3) * 16 + (cq0 ^ q)) * 4 + dc];               \
            __stcs(reinterpret_cast<float4*>(                                \
                       out + (size_t)c * GK + (size_t)(GOUT) * KK + q * 4), v);\
        }                                                                    \
    } while (0)

    // ---- prologue: lookups g0 -> buf0, g0+NBLK -> buf1; ballots ----
    if (t < KK) {
        {
            const int4 gp = reinterpret_cast<const int4*>(gpos)[g0];
            int z = min(max(gp.y + of.y, 0), ZDIM - 1);
            int y = min(max(gp.z + of.z, 0), YDIM - 1);
            int x = min(max(gp.w + of.w, 0), XDIM - 1);
            int idx = vox[((gp.x * ZDIM + z) * YDIM + y) * XDIM + x];
            s_idx[0][t] = idx;
            unsigned m = __ballot_sync(0xffffffffu, idx >= 0);
            if (lane == 0) s_ball[0][w] = m;
        }
        if (g0 + NBLK < G) {
            const int4 gp = reinterpret_cast<const int4*>(gpos)[g0 + NBLK];
            int z = min(max(gp.y + of.y, 0), ZDIM - 1);
            int y = min(max(gp.z + of.z, 0), YDIM - 1);
            int x = min(max(gp.w + of.w, 0), XDIM - 1);
            int idx = vox[((gp.x * ZDIM + z) * YDIM + y) * XDIM + x];
            s_idx[1][t] = idx;
            unsigned m = __ballot_sync(0xffffffffu, idx >= 0);
            if (lane == 0) s_ball[1][w] = m;
        }
    }
    __syncthreads();

    if (t == 0)
        out_mask[g0] = ((s_ball[0][0] | s_ball[0][1]) == 0u) ? 1.0f : 0.0f;

    // issue A(g0), B(g0)
    ISSUE_HALF(0, 0, 1);
    ISSUE_HALF(0, 2, 3);

    // ---- main loop; pi = buffer holding idx(g+NBLK) ----
    int pi = 1;
    for (int g = g0; g < G; g += NBLK) {
        const int gn  = g + NBLK;
        const int gnn = g + 2 * NBLK;
        const bool hn = (gn < G);

        // (1) voxel prefetch gnn -> regs; ballots -> s_ball[1-pi]
        int idxnext = -1;
        if (t < KK && gnn < G) {
            const int4 gp = reinterpret_cast<const int4*>(gpos)[gnn];
            int z = min(max(gp.y + of.y, 0), ZDIM - 1);
            int y = min(max(gp.z + of.z, 0), YDIM - 1);
            int x = min(max(gp.w + of.w, 0), XDIM - 1);
            idxnext = vox[((gp.x * ZDIM + z) * YDIM + y) * XDIM + x];
            unsigned m = __ballot_sync(0xffffffffu, idxnext >= 0);
            if (lane == 0) s_ball[1 - pi][w] = m;
        }

        // (2) A(g) ready
        asm volatile("cp.async.wait_group 1;");
        __syncthreads();

        // (3) drain half A -> out[g]
        DRAIN_HALF(g, 0, 1);
        __syncthreads();                       // (4) region A free

        // (5) issue A(gn)
        if (hn) ISSUE_HALF(pi, 0, 1);

        // (6) B(g) ready
        if (hn) { asm volatile("cp.async.wait_group 1;"); }
        else    { asm volatile("cp.async.wait_group 0;"); }
        __syncthreads();

        // (7) drain half B -> out[g]; gpf(g); mask(gn)
        DRAIN_HALF(g, 2, 3);
        __stcs(out_gpf + (size_t)gpf_ch * GK + (size_t)g * KK + gpf_k, gpf_val);
        if (t == 0 && hn)
            out_mask[gn] = ((s_ball[pi][0] | s_ball[pi][1]) == 0u) ? 1.0f : 0.0f;

        // (8) publish idx(gnn)
        if (t < KK && gnn < G)
            s_idx[1 - pi][t] = idxnext;

        __syncthreads();                       // (9) region B free + idx visible

        // (10) issue B(gn)
        if (hn) ISSUE_HALF(pi, 2, 3);

        pi ^= 1;
    }
#undef ISSUE_HALF
#undef DRAIN_HALF
}

extern "C" void kernel_launch(void* const* d_in, const int* in_sizes, int n_in,
                              void* d_out, int out_size) {
    const int*   vox  = (const int*)d_in[0];
    const int*   gpos = (const int*)d_in[1];
    const float* feat = (const float*)d_in[2];
    const int*   off  = (const int*)d_in[3];
    float* out = (float*)d_out;

    const int G = in_sizes[1] / 4;   // 30000
    grouper_kernel<<<NBLK, TPB>>>(vox, gpos, feat, off, out, G);
}

// round 17
// speedup vs baseline: 1.1890x; 1.0936x over previous
#include <cuda_runtime.h>

// TorchGrouper — round 17: R12 (best, 118.3us) with the iteration reordered
// so ALL tile-independent work sits inside the cp.async wait window:
//   issue gather(g) | voxel-prefetch(g+1)+publish idx/ballot -> [1-p]
//   | gpf(g) | mask(g) | wait 0; sync | drain(g) | sync
// Publish moved pre-wait: prev reader of s_idx[1-p] is behind prev sync#2,
// next reader behind this iter's barriers (audited). 2 barriers/g, 17KB smem,
// 8 blocks/SM — the configuration all experiments say is optimal.
// Output: [C,G,K] features, [4,G,K] gpf, [G] mask (float 1/0).

#define ZDIM 40
#define YDIM 400
#define XDIM 400
#define KK 64
#define CC 64
#define TPB 256
#define NBLK 1184

__global__ __launch_bounds__(TPB, 8) void grouper_kernel(
    const int* __restrict__ vox,     // [N,Z,Y,X]
    const int* __restrict__ gpos,    // [G,4]
    const float* __restrict__ feat,  // [M,C]
    const int* __restrict__ off,     // [K,4]
    float* __restrict__ out,
    int G)
{
    __shared__ int      s_idx[2][KK];
    __shared__ unsigned s_ball[2][2];
    __shared__ float4   s_tile[KK * 16];   // XOR-swizzled [k][cq'], 16 KB

    const int t    = threadIdx.x;
    const int w    = t >> 5;
    const int lane = t & 31;
    const size_t GK = (size_t)G * KK;
    float* out_gpf  = out + (size_t)CC * GK;
    float* out_mask = out + (size_t)(CC + 4) * GK;
    const unsigned tb = (unsigned)__cvta_generic_to_shared(s_tile);
    const float* tf = reinterpret_cast<const float*>(s_tile);

    // loop-invariant constants
    const int gpf_ch = t >> 6;
    const int gpf_k  = t & 63;
    const float gpf_val = (float)off[gpf_k * 4 + gpf_ch];
    int4 of = make_int4(0, 0, 0, 0);
    if (t < KK) of = reinterpret_cast<const int4*>(off)[t];

    // drain mapping (conflict-free): lane -> (ql, dc)
    const int ql = lane & 7;
    const int dc = lane >> 3;

    // ---- prologue: lookup for first g -> buffer 0 ----
    int g = blockIdx.x;
    if (t < KK) {
        const int4 gp = reinterpret_cast<const int4*>(gpos)[g];
        int z = min(max(gp.y + of.y, 0), ZDIM - 1);
        int y = min(max(gp.z + of.z, 0), YDIM - 1);
        int x = min(max(gp.w + of.w, 0), XDIM - 1);
        int idx = vox[((gp.x * ZDIM + z) * YDIM + y) * XDIM + x];
        s_idx[0][t] = idx;
        unsigned m = __ballot_sync(0xffffffffu, idx >= 0);
        if (lane == 0) s_ball[0][w] = m;
    }
    __syncthreads();

    int p = 0;
    for (; g < G; g += NBLK) {
        const int g_next = g + NBLK;
        const bool has_next = (g_next < G);

        // (A) issue gather for g from s_idx[p] (zero-fill when idx < 0)
#pragma unroll
        for (int j = 0; j < 4; j++) {
            const int job = t + TPB * j;     // 0..1023
            const int k   = job >> 4;        // 0..63
            const int cq  = job & 15;
            const int idx = s_idx[p][k];
            const unsigned dst = tb + (k * 16 + (cq ^ ((k >> 2) & 15))) * 16;
            const float* src = feat + (size_t)max(idx, 0) * CC + cq * 4;
            const int srcsz = (idx >= 0) ? 16 : 0;
            asm volatile("cp.async.cg.shared.global [%0], [%1], 16, %2;"
                         :: "r"(dst), "l"(src), "r"(srcsz));
        }
        asm volatile("cp.async.commit_group;");

        // (B) voxel prefetch g+1 AND publish directly (safe: last reader of
        //     s_idx[1-p] was prev iter's gather, behind prev sync#2)
        if (t < KK && has_next) {
            const int4 gp = reinterpret_cast<const int4*>(gpos)[g_next];
            int z = min(max(gp.y + of.y, 0), ZDIM - 1);
            int y = min(max(gp.z + of.z, 0), YDIM - 1);
            int x = min(max(gp.w + of.w, 0), XDIM - 1);
            int idx = vox[((gp.x * ZDIM + z) * YDIM + y) * XDIM + x];
            s_idx[1 - p][t] = idx;
            unsigned m = __ballot_sync(0xffffffffu, idx >= 0);
            if (lane == 0) s_ball[1 - p][w] = m;
        }

        // (C) gpf + mask for g (tile-independent; overlaps copy flight)
        __stcs(out_gpf + (size_t)gpf_ch * GK + (size_t)g * KK + gpf_k, gpf_val);
        if (t == 0)
            out_mask[g] = ((s_ball[p][0] | s_ball[p][1]) == 0u) ? 1.0f : 0.0f;

        // (D) wait for this g's copies; barrier makes them + idx visible
        asm volatile("cp.async.wait_group 0;");
        __syncthreads();

        // (E) drain tile -> out[g]  (CF LDS + streaming STG.128)
#pragma unroll
        for (int j = 0; j < 4; j++) {
            const int task = w * 4 + j;              // 0..31
            const int c0   = (task & 15) * 4;        // 0..60
            const int qh   = task >> 4;              // 0..1
            const int q    = qh * 8 + ql;            // 0..15
            const int c    = c0 + dc;
            const int cq0  = c0 >> 2;
            float4 v;
            v.x = tf[((q * 4 + 0) * 16 + (cq0 ^ (q & 15))) * 4 + dc];
            v.y = tf[((q * 4 + 1) * 16 + (cq0 ^ (q & 15))) * 4 + dc];
            v.z = tf[((q * 4 + 2) * 16 + (cq0 ^ (q & 15))) * 4 + dc];
            v.w = tf[((q * 4 + 3) * 16 + (cq0 ^ (q & 15))) * 4 + dc];
            __stcs(reinterpret_cast<float4*>(
                       out + (size_t)c * GK + (size_t)g * KK + q * 4), v);
        }

        // (F) tile WAR barrier before next iteration's cp.async issue
        __syncthreads();
        p ^= 1;
    }
}

extern "C" void kernel_launch(void* const* d_in, const int* in_sizes, int n_in,
                              void* d_out, int out_size) {
    const int*   vox  = (const int*)d_in[0];
    const int*   gpos = (const int*)d_in[1];
    const float* feat = (const float*)d_in[2];
    const int*   off  = (const int*)d_in[3];
    float* out = (float*)d_out;

    const int G = in_sizes[1] / 4;   // 30000
    grouper_kernel<<<NBLK, TPB>>>(vox, gpos, feat, off, out, G);
}